// round 3
// baseline (speedup 1.0000x reference)
#include <cuda_runtime.h>
#include <math.h>

#define MAXN 50000
#define MAXE 800000

typedef unsigned long long u64;

// ---------------- scratch (static device globals; no allocs allowed) ----------------
__device__ int   g_cnt[MAXN];
__device__ int   g_off[MAXN + 1];
__device__ int   g_cursor[MAXN];
__device__ int   g_bsum[64];
__device__ float g_dis[MAXN];
__device__ int2  g_csr[MAXE];               // {src row, float bits of dis[src]}
__device__ float g_xw1[(size_t)MAXN * 64];  // x@W1 (raw)
__device__ float g_h  [(size_t)MAXN * 64];  // relu(layer1)
__device__ float g_xw2[(size_t)MAXN * 64];  // h@W2 (raw)
__device__ float g_z  [(size_t)MAXN * 64];  // layer2 out

// ---------------- streams/events created once at static init (host-side only) ----------------
static cudaStream_t g_s2;
static cudaEvent_t  g_evF, g_evJ;
struct _AthInit {
    _AthInit() {
        cudaStreamCreateWithFlags(&g_s2, cudaStreamNonBlocking);
        cudaEventCreateWithFlags(&g_evF, cudaEventDisableTiming);
        cudaEventCreateWithFlags(&g_evJ, cudaEventDisableTiming);
    }
};
static _AthInit _ath_init;

// ---------------- packed fp32x2 helpers ----------------
__device__ __forceinline__ u64 pk2(float a, float b) {
    u64 r; asm("mov.b64 %0, {%1, %2};" : "=l"(r) : "f"(a), "f"(b)); return r;
}
__device__ __forceinline__ void fma2(u64& d, u64 a, u64 b) {
    asm("fma.rn.f32x2 %0, %1, %2, %0;" : "+l"(d) : "l"(a), "l"(b));
}
__device__ __forceinline__ float2 up2(u64 v) {
    float2 r; asm("mov.b64 {%0, %1}, %2;" : "=f"(r.x), "=f"(r.y) : "l"(v)); return r;
}

// ---------------- CSR build ----------------
__global__ void k_count(const int* __restrict__ ei, int nE) {
    int e = blockIdx.x * blockDim.x + threadIdx.x;
    if (e < nE) atomicAdd(&g_cnt[ei[nE + e]], 1);  // col = target
}

__global__ void k_scanA(int n) {
    __shared__ int s[1024];
    int t = threadIdx.x;
    int i = blockIdx.x * 1024 + t;
    int v = (i < n) ? g_cnt[i] : 0;
    s[t] = v;
    __syncthreads();
#pragma unroll
    for (int d = 1; d < 1024; d <<= 1) {
        int x = (t >= d) ? s[t - d] : 0;
        __syncthreads();
        s[t] += x;
        __syncthreads();
    }
    if (i < n) g_off[i] = s[t] - v;     // exclusive within block
    if (t == 1023) g_bsum[blockIdx.x] = s[1023];
}

__global__ void k_scanB(int nb, int n) {
    __shared__ int s[64];
    int t = threadIdx.x;
    int v = (t < nb) ? g_bsum[t] : 0;
    s[t] = v;
    __syncthreads();
#pragma unroll
    for (int d = 1; d < 64; d <<= 1) {
        int x = (t >= d) ? s[t - d] : 0;
        __syncthreads();
        s[t] += x;
        __syncthreads();
    }
    if (t < nb) g_bsum[t] = s[t] - v;   // exclusive
    if (t == nb - 1) g_off[n] = s[t];   // total
}

__global__ void k_scanC(int n) {
    int i = blockIdx.x * blockDim.x + threadIdx.x;
    if (i < n) {
        int o = g_off[i] + g_bsum[i >> 10];
        g_off[i] = o;
        g_cursor[i] = o;
        g_dis[i] = rsqrtf((float)(g_cnt[i] + 1));   // deg = in-degree + self-loop
    }
}

__global__ void k_scatter(const int* __restrict__ ei, int nE) {
    int e = blockIdx.x * blockDim.x + threadIdx.x;
    if (e < nE) {
        int row = ei[e];
        int col = ei[nE + e];
        int p = atomicAdd(&g_cursor[col], 1);
        g_csr[p] = make_int2(row, __float_as_int(g_dis[row]));
    }
}

// ---------------- GEMM (raw, no scaling): out[r][c] = A[r][:] @ W[:][c] ----------------
template <int K>
__global__ void k_gemm(const float* __restrict__ A, const float* __restrict__ W,
                       float* __restrict__ out, int n) {
    __shared__ float xs[64][64];   // rows x k
    __shared__ float ws[64][64];   // k x cols
    int t = threadIdx.x;
    int tx = t & 15;      // col group (x4)
    int ty = t >> 4;      // row group (x4)
    int row0 = blockIdx.x * 64;

    u64 acc[4][2] = {};

    for (int kc = 0; kc < K; kc += 64) {
#pragma unroll
        for (int it = 0; it < 4; it++) {
            int v = it * 256 + t;        // 0..1023 float4 slots
            int r = v >> 4;              // 0..63
            int q = v & 15;              // 0..15 (x4 floats)
            int gr = min(row0 + r, n - 1);
            float4 xv = *(const float4*)(A + (size_t)gr * K + kc + q * 4);
            *(float4*)&xs[r][q * 4] = xv;
            float4 wv = *(const float4*)(W + (size_t)(kc + r) * 64 + q * 4);
            *(float4*)&ws[r][q * 4] = wv;
        }
        __syncthreads();

#pragma unroll
        for (int k = 0; k < 64; k++) {
            ulonglong2 wv = *(const ulonglong2*)&ws[k][tx * 4];
#pragma unroll
            for (int i = 0; i < 4; i++) {
                float xf = xs[ty * 4 + i][k];
                u64 xd = pk2(xf, xf);
                fma2(acc[i][0], xd, wv.x);
                fma2(acc[i][1], xd, wv.y);
            }
        }
        __syncthreads();
    }

#pragma unroll
    for (int i = 0; i < 4; i++) {
        int r = row0 + ty * 4 + i;
        if (r < n) {
            float2 lo = up2(acc[i][0]);
            float2 hi = up2(acc[i][1]);
            float4 o; o.x = lo.x; o.y = lo.y; o.z = hi.x; o.w = hi.y;
            *(float4*)(out + (size_t)r * 64 + tx * 4) = o;
        }
    }
}

// ---------------- Aggregation ----------------
// out[i] = act( dis[i]*( sum_in xw[row]*dis[row] + xw[i]*dis[i] ) + b )
// 16 lanes per node, float4 per lane, 512 threads = 32 nodes/block.
template <int RELU>
__global__ void k_aggregate(const float4* __restrict__ xw, float4* __restrict__ out,
                            const float4* __restrict__ bias, int n) {
    int node = blockIdx.x * 32 + (threadIdx.x >> 4);
    int sl = threadIdx.x & 15;
    if (node >= n) return;
    float d = g_dis[node];
    float4 acc = xw[(size_t)node * 16 + sl];
    acc.x *= d; acc.y *= d; acc.z *= d; acc.w *= d;  // self-loop: xw[i]*dis[i]
    int s = g_off[node], e = g_off[node + 1];
    for (int base = s; base < e; base += 16) {
        int idx = base + sl;
        int2 pr = (idx < e) ? g_csr[idx] : make_int2(0, 0);
        int cnt = min(16, e - base);
        for (int j = 0; j < cnt; j++) {
            int row  = __shfl_sync(0xffffffffu, pr.x, j, 16);
            float dw = __int_as_float(__shfl_sync(0xffffffffu, pr.y, j, 16));
            float4 v = xw[(size_t)row * 16 + sl];
            acc.x = fmaf(v.x, dw, acc.x);
            acc.y = fmaf(v.y, dw, acc.y);
            acc.z = fmaf(v.z, dw, acc.z);
            acc.w = fmaf(v.w, dw, acc.w);
        }
    }
    float4 bv = bias[sl];
    float4 o;
    o.x = fmaf(d, acc.x, bv.x);
    o.y = fmaf(d, acc.y, bv.y);
    o.z = fmaf(d, acc.z, bv.z);
    o.w = fmaf(d, acc.w, bv.w);
    if (RELU) {
        o.x = fmaxf(o.x, 0.f); o.y = fmaxf(o.y, 0.f);
        o.z = fmaxf(o.z, 0.f); o.w = fmaxf(o.w, 0.f);
    }
    out[(size_t)node * 16 + sl] = o;
}

// ---------------- Decode: out[e] = dot(z[src], z[dst]) ----------------
__global__ void k_decode(const int* __restrict__ eli, const float4* __restrict__ z,
                         float* __restrict__ out, int nL) {
    int w = blockIdx.x * 16 + (threadIdx.x >> 4);
    int sl = threadIdx.x & 15;
    if (w >= nL) return;
    int s = eli[w];
    int d = eli[nL + w];
    float4 a = z[(size_t)s * 16 + sl];
    float4 b = z[(size_t)d * 16 + sl];
    float p = a.x * b.x + a.y * b.y + a.z * b.z + a.w * b.w;
#pragma unroll
    for (int o = 8; o > 0; o >>= 1) p += __shfl_down_sync(0xffffffffu, p, o, 16);
    if (sl == 0) out[w] = p;
}

// ---------------- launch ----------------
extern "C" void kernel_launch(void* const* d_in, const int* in_sizes, int n_in,
                              void* d_out, int out_size) {
    const float* x   = (const float*)d_in[0];
    const int*   ei  = (const int*)  d_in[1];
    const int*   eli = (const int*)  d_in[2];
    const float* W1  = (const float*)d_in[3];
    const float* b1  = (const float*)d_in[4];
    const float* W2  = (const float*)d_in[5];
    const float* b2  = (const float*)d_in[6];
    float* out = (float*)d_out;

    int n  = in_sizes[0] / 256;
    int nE = in_sizes[1] / 2;
    int nL = in_sizes[2] / 2;

    void *p_xw1, *p_h, *p_xw2, *p_z, *p_cnt;
    cudaGetSymbolAddress(&p_xw1, g_xw1);
    cudaGetSymbolAddress(&p_h,   g_h);
    cudaGetSymbolAddress(&p_xw2, g_xw2);
    cudaGetSymbolAddress(&p_z,   g_z);
    cudaGetSymbolAddress(&p_cnt, g_cnt);

    // Fork: CSR build on side stream, GEMM1 on main stream (independent).
    cudaEventRecord(g_evF, 0);
    cudaStreamWaitEvent(g_s2, g_evF, 0);

    cudaMemsetAsync(p_cnt, 0, n * sizeof(int), g_s2);
    k_count<<<(nE + 255) / 256, 256, 0, g_s2>>>(ei, nE);
    int nb = (n + 1023) / 1024;
    k_scanA<<<nb, 1024, 0, g_s2>>>(n);
    k_scanB<<<1, 64, 0, g_s2>>>(nb, n);
    k_scanC<<<(n + 255) / 256, 256, 0, g_s2>>>(n);
    k_scatter<<<(nE + 255) / 256, 256, 0, g_s2>>>(ei, nE);
    cudaEventRecord(g_evJ, g_s2);

    int gb = (n + 63) / 64;
    k_gemm<256><<<gb, 256>>>(x, W1, (float*)p_xw1, n);   // concurrent with CSR

    // Join
    cudaStreamWaitEvent(0, g_evJ, 0);

    // layer 1 aggregate
    k_aggregate<1><<<(n + 31) / 32, 512>>>((const float4*)p_xw1, (float4*)p_h,
                                           (const float4*)b1, n);
    // layer 2
    k_gemm<64><<<gb, 256>>>((const float*)p_h, W2, (float*)p_xw2, n);
    k_aggregate<0><<<(n + 31) / 32, 512>>>((const float4*)p_xw2, (float4*)p_z,
                                           (const float4*)b2, n);
    // decode
    k_decode<<<(nL + 15) / 16, 256>>>(eli, (const float4*)p_z, out, nL);
}

// round 4
// speedup vs baseline: 1.1892x; 1.1892x over previous
#include <cuda_runtime.h>
#include <math.h>

#define MAXN 50000
#define MAXE 800000

typedef unsigned long long u64;

// ---------------- scratch (static device globals; no allocs allowed) ----------------
__device__ int   g_cnt[MAXN];            // zeroed at static init; scan re-zeroes after read
__device__ int   g_off[MAXN + 1];
__device__ int   g_cursor[MAXN];
__device__ volatile u64 g_state[64];     // lookback states; zeroed by k_count block 0
__device__ float g_dis[MAXN];
__device__ int2  g_csr[MAXE];            // {src row, float bits of dis[src]}
__device__ float g_xw1[(size_t)MAXN * 64];  // x@W1 (raw)
__device__ float g_h  [(size_t)MAXN * 64];  // relu(layer1)
__device__ float g_xw2[(size_t)MAXN * 64];  // h@W2 (raw)
__device__ float g_z  [(size_t)MAXN * 64];  // layer2 out

// ---------------- streams/events (host-side, created once) ----------------
static cudaStream_t g_s2;
static cudaEvent_t  g_evF, g_evJ;
struct _AthInit {
    _AthInit() {
        cudaStreamCreateWithFlags(&g_s2, cudaStreamNonBlocking);
        cudaEventCreateWithFlags(&g_evF, cudaEventDisableTiming);
        cudaEventCreateWithFlags(&g_evJ, cudaEventDisableTiming);
    }
};
static _AthInit _ath_init;

// ---------------- packed fp32x2 helpers ----------------
__device__ __forceinline__ u64 pk2(float a, float b) {
    u64 r; asm("mov.b64 %0, {%1, %2};" : "=l"(r) : "f"(a), "f"(b)); return r;
}
__device__ __forceinline__ void fma2(u64& d, u64 a, u64 b) {
    asm("fma.rn.f32x2 %0, %1, %2, %0;" : "+l"(d) : "l"(a), "l"(b));
}
__device__ __forceinline__ float2 up2(u64 v) {
    float2 r; asm("mov.b64 {%0, %1}, %2;" : "=f"(r.x), "=f"(r.y) : "l"(v)); return r;
}

// ---------------- CSR build ----------------
__global__ void k_count(const int* __restrict__ ei, int nE) {
    if (blockIdx.x == 0 && threadIdx.x < 64) g_state[threadIdx.x] = 0;
    int e = blockIdx.x * blockDim.x + threadIdx.x;
    if (e < nE) atomicAdd(&g_cnt[ei[nE + e]], 1);  // col = target
}

// fused scan: exclusive offsets + cursor init + dis, single kernel.
// nb <= 64 blocks, all resident in wave 1 -> spin-wait is deadlock-free.
__global__ void k_scan_fused(int n, int nb) {
    __shared__ int s[1024];
    __shared__ int s_excl;
    __shared__ int r64[2];
    int b = blockIdx.x, t = threadIdx.x;
    int i = b * 1024 + t;
    int v = (i < n) ? g_cnt[i] : 0;
    if (i < n) g_cnt[i] = 0;              // restore invariant for next replay
    s[t] = v;
    __syncthreads();
#pragma unroll
    for (int dd = 1; dd < 1024; dd <<= 1) {
        int x = (t >= dd) ? s[t - dd] : 0;
        __syncthreads();
        s[t] += x;
        __syncthreads();
    }
    int incl = s[t];
    if (t == 1023)
        g_state[b] = (1ull << 32) | (unsigned)incl;   // publish block aggregate
    // lookback: threads 0..63 each spin on one predecessor's aggregate
    if (t < 64) {
        int val = 0;
        if (t < b) {
            u64 st;
            do { st = g_state[t]; } while (!(st >> 32));
            val = (int)(unsigned)st;
        }
#pragma unroll
        for (int o = 16; o; o >>= 1) val += __shfl_down_sync(0xffffffffu, val, o);
        if ((t & 31) == 0) r64[t >> 5] = val;
    }
    __syncthreads();
    if (t == 0) s_excl = r64[0] + r64[1];
    __syncthreads();
    int ex = s_excl;
    if (i < n) {
        int o = ex + incl - v;
        g_off[i] = o;
        g_cursor[i] = o;
        g_dis[i] = rsqrtf((float)(v + 1));   // deg = in-degree + self-loop
    }
    if (b == nb - 1 && t == 1023) g_off[n] = ex + incl;
}

__global__ void k_scatter(const int* __restrict__ ei, int nE) {
    int e = blockIdx.x * blockDim.x + threadIdx.x;
    if (e < nE) {
        int row = ei[e];
        int col = ei[nE + e];
        int p = atomicAdd(&g_cursor[col], 1);
        g_csr[p] = make_int2(row, __float_as_int(g_dis[row]));
    }
}

// ---------------- GEMM (raw): out[r][c] = A[r][:] @ W[:][c] ----------------
template <int K>
__global__ void k_gemm(const float* __restrict__ A, const float* __restrict__ W,
                       float* __restrict__ out, int n) {
    __shared__ float xs[64][64];
    __shared__ float ws[64][64];
    int t = threadIdx.x;
    int tx = t & 15;
    int ty = t >> 4;
    int row0 = blockIdx.x * 64;

    u64 acc[4][2] = {};

    for (int kc = 0; kc < K; kc += 64) {
#pragma unroll
        for (int it = 0; it < 4; it++) {
            int v = it * 256 + t;
            int r = v >> 4;
            int q = v & 15;
            int gr = min(row0 + r, n - 1);
            float4 xv = *(const float4*)(A + (size_t)gr * K + kc + q * 4);
            *(float4*)&xs[r][q * 4] = xv;
            float4 wv = *(const float4*)(W + (size_t)(kc + r) * 64 + q * 4);
            *(float4*)&ws[r][q * 4] = wv;
        }
        __syncthreads();

#pragma unroll
        for (int k = 0; k < 64; k++) {
            ulonglong2 wv = *(const ulonglong2*)&ws[k][tx * 4];
#pragma unroll
            for (int i = 0; i < 4; i++) {
                float xf = xs[ty * 4 + i][k];
                u64 xd = pk2(xf, xf);
                fma2(acc[i][0], xd, wv.x);
                fma2(acc[i][1], xd, wv.y);
            }
        }
        __syncthreads();
    }

#pragma unroll
    for (int i = 0; i < 4; i++) {
        int r = row0 + ty * 4 + i;
        if (r < n) {
            float2 lo = up2(acc[i][0]);
            float2 hi = up2(acc[i][1]);
            float4 o; o.x = lo.x; o.y = lo.y; o.z = hi.x; o.w = hi.y;
            *(float4*)(out + (size_t)r * 64 + tx * 4) = o;
        }
    }
}

// ---------------- Aggregation (R1 shape: warp per node, float2 per lane) ----------------
// out[i] = act( dis[i]*( sum_in xw[row]*dis[row] + xw[i]*dis[i] ) + b )
__global__ void k_aggregate(const float* __restrict__ in, float* __restrict__ out,
                            const float* __restrict__ bias, int n, int relu) {
    int node = blockIdx.x * 8 + (threadIdx.x >> 5);
    int lane = threadIdx.x & 31;
    if (node >= n) return;
    const float2* inp = (const float2*)in;
    float d = g_dis[node];
    float2 acc = inp[(size_t)node * 32 + lane];
    acc.x *= d; acc.y *= d;                     // self-loop: xw[i]*dis[i]
    int s = g_off[node], e = g_off[node + 1];
    for (int base = s; base < e; base += 32) {
        int idx = base + lane;
        int2 pr = (idx < e) ? g_csr[idx] : make_int2(0, 0);
        int cnt = min(32, e - base);
        for (int j = 0; j < cnt; j++) {
            int row  = __shfl_sync(0xffffffffu, pr.x, j);
            float dw = __int_as_float(__shfl_sync(0xffffffffu, pr.y, j));
            float2 v = inp[(size_t)row * 32 + lane];
            acc.x = fmaf(v.x, dw, acc.x);
            acc.y = fmaf(v.y, dw, acc.y);
        }
    }
    float2 bv = ((const float2*)bias)[lane];
    float ox = fmaf(d, acc.x, bv.x);
    float oy = fmaf(d, acc.y, bv.y);
    if (relu) { ox = fmaxf(ox, 0.f); oy = fmaxf(oy, 0.f); }
    float2 o; o.x = ox; o.y = oy;
    ((float2*)out)[(size_t)node * 32 + lane] = o;
}

// ---------------- Decode: out[e] = dot(z[src], z[dst]) ----------------
__global__ void k_decode(const int* __restrict__ eli, const float* __restrict__ z,
                         float* __restrict__ out, int nL) {
    int w = blockIdx.x * 8 + (threadIdx.x >> 5);
    int lane = threadIdx.x & 31;
    if (w >= nL) return;
    int s = eli[w];
    int d = eli[nL + w];
    const float2* z2 = (const float2*)z;
    float2 a = z2[(size_t)s * 32 + lane];
    float2 b = z2[(size_t)d * 32 + lane];
    float p = a.x * b.x + a.y * b.y;
#pragma unroll
    for (int o = 16; o > 0; o >>= 1) p += __shfl_down_sync(0xffffffffu, p, o);
    if (lane == 0) out[w] = p;
}

// ---------------- launch ----------------
extern "C" void kernel_launch(void* const* d_in, const int* in_sizes, int n_in,
                              void* d_out, int out_size) {
    const float* x   = (const float*)d_in[0];
    const int*   ei  = (const int*)  d_in[1];
    const int*   eli = (const int*)  d_in[2];
    const float* W1  = (const float*)d_in[3];
    const float* b1  = (const float*)d_in[4];
    const float* W2  = (const float*)d_in[5];
    const float* b2  = (const float*)d_in[6];
    float* out = (float*)d_out;

    int n  = in_sizes[0] / 256;
    int nE = in_sizes[1] / 2;
    int nL = in_sizes[2] / 2;

    void *p_xw1, *p_h, *p_xw2, *p_z;
    cudaGetSymbolAddress(&p_xw1, g_xw1);
    cudaGetSymbolAddress(&p_h,   g_h);
    cudaGetSymbolAddress(&p_xw2, g_xw2);
    cudaGetSymbolAddress(&p_z,   g_z);

    // Fork: CSR build on side stream, GEMM1 concurrently on main stream.
    cudaEventRecord(g_evF, 0);
    cudaStreamWaitEvent(g_s2, g_evF, 0);

    k_count<<<(nE + 255) / 256, 256, 0, g_s2>>>(ei, nE);
    int nb = (n + 1023) / 1024;
    k_scan_fused<<<nb, 1024, 0, g_s2>>>(n, nb);
    k_scatter<<<(nE + 255) / 256, 256, 0, g_s2>>>(ei, nE);
    cudaEventRecord(g_evJ, g_s2);

    int gb = (n + 63) / 64;
    k_gemm<256><<<gb, 256>>>(x, W1, (float*)p_xw1, n);   // concurrent with CSR

    // Join
    cudaStreamWaitEvent(0, g_evJ, 0);

    // layer 1 aggregate
    k_aggregate<<<(n + 7) / 8, 256>>>((const float*)p_xw1, (float*)p_h, b1, n, 1);
    // layer 2
    k_gemm<64><<<gb, 256>>>((const float*)p_h, W2, (float*)p_xw2, n);
    k_aggregate<<<(n + 7) / 8, 256>>>((const float*)p_xw2, (float*)p_z, b2, n, 0);
    // decode
    k_decode<<<(nL + 7) / 8, 256>>>(eli, (const float*)p_z, out, nL);
}